// round 3
// baseline (speedup 1.0000x reference)
#include <cuda_runtime.h>
#include <math.h>

#define S_TOTAL 13294
#define BATCHN 2
#define MTOT (BATCHN * S_TOTAL)   // 26588
#define DM 256
#define DF 1024

// ---------------- scratch (static device globals; no runtime allocation) -------------
__device__ float g_off[MTOT * DM];
__device__ float g_attn[MTOT * 128];
__device__ float g_val[MTOT * DM];
__device__ float g_ao[MTOT * DM];
__device__ float g_src2[MTOT * DM];
__device__ float g_x[MTOT * DM];
__device__ float g_h1[MTOT * DF];
__device__ float g_ff[MTOT * DM];

// ---------------- SGEMM: C[M,N] = (A [+A2]) @ B[K,N] + bias, optional ReLU -----------
// 64x64 tile, BK=16, 256 threads, 4x4 per thread. ADD2: A-operand = A + A2 (elementwise).
template <int RELU, int ADD2>
__global__ void __launch_bounds__(256) sgemm(const float* __restrict__ A,
                                             const float* __restrict__ A2,
                                             const float* __restrict__ B,
                                             const float* __restrict__ bias,
                                             float* __restrict__ C,
                                             int M, int K, int N) {
    __shared__ float As[16][65];   // [k][m], padded to dodge bank conflicts
    __shared__ float Bs[16][64];   // [k][n]

    int t = threadIdx.x;
    int tx = t & 15;          // col group (4 cols)
    int ty = t >> 4;          // row group (4 rows)
    int row0 = blockIdx.y * 64;
    int col0 = blockIdx.x * 64;

    // A tile loaders: 64 rows x 16 cols; thread -> (row = t/4, 4 cols = (t%4)*4)
    int ar = t >> 2;
    int ac = (t & 3) << 2;
    // B tile loaders: 16 rows x 64 cols; thread -> (row = t/16, 4 cols = (t%16)*4)
    int br = t >> 4;
    int bc = (t & 15) << 2;

    bool arow_ok = (row0 + ar) < M;
    const float* Aptr  = A  + (size_t)(row0 + ar) * K + ac;
    const float* A2ptr = ADD2 ? (A2 + (size_t)(row0 + ar) * K + ac) : nullptr;

    float acc[4][4];
#pragma unroll
    for (int i = 0; i < 4; i++)
#pragma unroll
        for (int j = 0; j < 4; j++) acc[i][j] = 0.f;

    for (int k0 = 0; k0 < K; k0 += 16) {
        float4 av = make_float4(0.f, 0.f, 0.f, 0.f);
        if (arow_ok) {
            av = *(const float4*)(Aptr + k0);
            if (ADD2) {
                float4 a2 = *(const float4*)(A2ptr + k0);
                av.x += a2.x; av.y += a2.y; av.z += a2.z; av.w += a2.w;
            }
        }
        As[ac + 0][ar] = av.x;
        As[ac + 1][ar] = av.y;
        As[ac + 2][ar] = av.z;
        As[ac + 3][ar] = av.w;

        float4 bv = *(const float4*)&B[(size_t)(k0 + br) * N + col0 + bc];
        *(float4*)&Bs[br][bc] = bv;

        __syncthreads();
#pragma unroll
        for (int k = 0; k < 16; k++) {
            float a0 = As[k][ty * 4 + 0];
            float a1 = As[k][ty * 4 + 1];
            float a2 = As[k][ty * 4 + 2];
            float a3 = As[k][ty * 4 + 3];
            float4 b4 = *(const float4*)&Bs[k][tx * 4];
            acc[0][0] += a0 * b4.x; acc[0][1] += a0 * b4.y; acc[0][2] += a0 * b4.z; acc[0][3] += a0 * b4.w;
            acc[1][0] += a1 * b4.x; acc[1][1] += a1 * b4.y; acc[1][2] += a1 * b4.z; acc[1][3] += a1 * b4.w;
            acc[2][0] += a2 * b4.x; acc[2][1] += a2 * b4.y; acc[2][2] += a2 * b4.z; acc[2][3] += a2 * b4.w;
            acc[3][0] += a3 * b4.x; acc[3][1] += a3 * b4.y; acc[3][2] += a3 * b4.z; acc[3][3] += a3 * b4.w;
        }
        __syncthreads();
    }

    float4 bb = *(const float4*)&bias[col0 + tx * 4];
#pragma unroll
    for (int i = 0; i < 4; i++) {
        int row = row0 + ty * 4 + i;
        if (row < M) {
            float4 v;
            v.x = acc[i][0] + bb.x;
            v.y = acc[i][1] + bb.y;
            v.z = acc[i][2] + bb.z;
            v.w = acc[i][3] + bb.w;
            if (RELU) {
                v.x = fmaxf(v.x, 0.f); v.y = fmaxf(v.y, 0.f);
                v.z = fmaxf(v.z, 0.f); v.w = fmaxf(v.w, 0.f);
            }
            *(float4*)&C[(size_t)row * N + col0 + tx * 4] = v;
        }
    }
}

// ---------------- MSDeformAttn sampling: softmax + bilinear + weighted sum -----------
// One block per (batch,token) row; warp h handles head h; lane = head-dim channel.
__global__ void __launch_bounds__(256) msda_sample(
    const float* __restrict__ refp,    // (N, S, 4, 2)
    const float* __restrict__ off,     // (rows, 256) = (h, l, p, 2)
    const float* __restrict__ attnlog, // (rows, 128) = (h, l*4+p)
    const float* __restrict__ value,   // (rows, 8, 32)
    float* __restrict__ out)           // (rows, 256)
{
    const int Hs[4]     = {100, 50, 25, 13};
    const int Ws[4]     = {100, 50, 25, 13};
    const int starts[4] = {0, 10000, 12500, 13125};

    int row = blockIdx.x;            // n*S + s
    int h = threadIdx.x >> 5;
    int lane = threadIdx.x & 31;
    int n = (row >= S_TOTAL) ? 1 : 0;

    // softmax over 16 attention logits (redundant per-lane; L1 broadcast)
    const float* al = attnlog + (size_t)row * 128 + h * 16;
    float l[16];
    float m = -1e30f;
#pragma unroll
    for (int j = 0; j < 16; j++) { l[j] = al[j]; m = fmaxf(m, l[j]); }
    float den = 0.f;
#pragma unroll
    for (int j = 0; j < 16; j++) { l[j] = expf(l[j] - m); den += l[j]; }
    float inv = 1.f / den;

    const float* offp = off + (size_t)row * 256 + h * 32;
    const float* rp = refp + (size_t)row * 8;

    float acc = 0.f;
#pragma unroll
    for (int lv = 0; lv < 4; lv++) {
        int H = Hs[lv], W = Ws[lv];
        float rx = rp[lv * 2 + 0];
        float ry = rp[lv * 2 + 1];
        int base = n * S_TOTAL + starts[lv];
#pragma unroll
        for (int p = 0; p < 4; p++) {
            float ox = offp[(lv * 4 + p) * 2 + 0];
            float oy = offp[(lv * 4 + p) * 2 + 1];
            // loc = ref + off/normalizer(W,H); then x = loc_x*W - 0.5
            float x = (rx + ox / (float)W) * (float)W - 0.5f;
            float y = (ry + oy / (float)H) * (float)H - 0.5f;
            float x0f = floorf(x), y0f = floorf(y);
            int x0 = (int)x0f, y0 = (int)y0f;
            int x1 = x0 + 1, y1 = y0 + 1;
            float wx1 = x - x0f, wx0 = 1.f - wx1;
            float wy1 = y - y0f, wy0 = 1.f - wy1;
            float aw = l[lv * 4 + p] * inv;

            float s = 0.f;
            bool y0ok = (y0 >= 0) & (y0 < H);
            bool y1ok = (y1 >= 0) & (y1 < H);
            bool x0ok = (x0 >= 0) & (x0 < W);
            bool x1ok = (x1 >= 0) & (x1 < W);
            if (y0ok & x0ok)
                s += wy0 * wx0 * value[((size_t)(base + y0 * W + x0) * 8 + h) * 32 + lane];
            if (y0ok & x1ok)
                s += wy0 * wx1 * value[((size_t)(base + y0 * W + x1) * 8 + h) * 32 + lane];
            if (y1ok & x0ok)
                s += wy1 * wx0 * value[((size_t)(base + y1 * W + x0) * 8 + h) * 32 + lane];
            if (y1ok & x1ok)
                s += wy1 * wx1 * value[((size_t)(base + y1 * W + x1) * 8 + h) * 32 + lane];
            acc += aw * s;
        }
    }
    out[(size_t)row * 256 + h * 32 + lane] = acc;
}

// ---------------- fused residual add + LayerNorm (C = 256) ---------------------------
__global__ void __launch_bounds__(256) add_ln(const float* __restrict__ a,
                                              const float* __restrict__ b,
                                              const float* __restrict__ g,
                                              const float* __restrict__ be,
                                              float* __restrict__ out) {
    int row = blockIdx.x;
    int t = threadIdx.x;
    float v = a[(size_t)row * 256 + t] + b[(size_t)row * 256 + t];

    __shared__ float red[8];
    __shared__ float stat[2];

    float s = v;
#pragma unroll
    for (int o = 16; o; o >>= 1) s += __shfl_xor_sync(0xffffffffu, s, o);
    if ((t & 31) == 0) red[t >> 5] = s;
    __syncthreads();
    if (t == 0) {
        float tot = 0.f;
        for (int i = 0; i < 8; i++) tot += red[i];
        stat[0] = tot * (1.f / 256.f);
    }
    __syncthreads();
    float mean = stat[0];
    float d = v - mean;

    s = d * d;
#pragma unroll
    for (int o = 16; o; o >>= 1) s += __shfl_xor_sync(0xffffffffu, s, o);
    __syncthreads();   // red[] reuse safety
    if ((t & 31) == 0) red[t >> 5] = s;
    __syncthreads();
    if (t == 0) {
        float tot = 0.f;
        for (int i = 0; i < 8; i++) tot += red[i];
        stat[1] = tot * (1.f / 256.f);
    }
    __syncthreads();
    float var = stat[1];

    out[(size_t)row * 256 + t] = d * rsqrtf(var + 1e-5f) * g[t] + be[t];
}

// ---------------- launch -------------------------------------------------------------
extern "C" void kernel_launch(void* const* d_in, const int* in_sizes, int n_in,
                              void* d_out, int out_size) {
    const float* src   = (const float*)d_in[0];
    const float* pos   = (const float*)d_in[1];
    const float* refp  = (const float*)d_in[2];
    // d_in[3] spatial_shapes, d_in[4] level_start_index: static metadata, hardcoded
    const float* W_off  = (const float*)d_in[5];
    const float* b_off  = (const float*)d_in[6];
    const float* W_attn = (const float*)d_in[7];
    const float* b_attn = (const float*)d_in[8];
    const float* W_val  = (const float*)d_in[9];
    const float* b_val  = (const float*)d_in[10];
    const float* W_out  = (const float*)d_in[11];
    const float* b_out  = (const float*)d_in[12];
    const float* W1     = (const float*)d_in[13];
    const float* b1     = (const float*)d_in[14];
    const float* W2     = (const float*)d_in[15];
    const float* b2     = (const float*)d_in[16];
    const float* g1p    = (const float*)d_in[17];
    const float* be1p   = (const float*)d_in[18];
    const float* g2p    = (const float*)d_in[19];
    const float* be2p   = (const float*)d_in[20];
    float* out = (float*)d_out;

    float *offb, *attn, *val, *ao, *src2, *x, *h1, *ff;
    cudaGetSymbolAddress((void**)&offb, g_off);
    cudaGetSymbolAddress((void**)&attn, g_attn);
    cudaGetSymbolAddress((void**)&val, g_val);
    cudaGetSymbolAddress((void**)&ao, g_ao);
    cudaGetSymbolAddress((void**)&src2, g_src2);
    cudaGetSymbolAddress((void**)&x, g_x);
    cudaGetSymbolAddress((void**)&h1, g_h1);
    cudaGetSymbolAddress((void**)&ff, g_ff);

    const int M = MTOT;
    const int mby = (M + 63) / 64;

    // q = src + pos fused into the A-operand of the off/attn projections
    sgemm<0, 1><<<dim3(4, mby), 256>>>(src, pos, W_off, b_off, offb, M, 256, 256);
    sgemm<0, 1><<<dim3(2, mby), 256>>>(src, pos, W_attn, b_attn, attn, M, 256, 128);
    sgemm<0, 0><<<dim3(4, mby), 256>>>(src, nullptr, W_val, b_val, val, M, 256, 256);

    msda_sample<<<M, 256>>>(refp, offb, attn, val, ao);

    sgemm<0, 0><<<dim3(4, mby), 256>>>(ao, nullptr, W_out, b_out, src2, M, 256, 256);
    add_ln<<<M, 256>>>(src, src2, g1p, be1p, x);

    sgemm<1, 0><<<dim3(16, mby), 256>>>(x, nullptr, W1, b1, h1, M, 256, 1024);
    sgemm<0, 0><<<dim3(4, mby), 256>>>(h1, nullptr, W2, b2, ff, M, 1024, 256);
    add_ln<<<M, 256>>>(x, ff, g2p, be2p, out);
}

// round 4
// speedup vs baseline: 1.1124x; 1.1124x over previous
#include <cuda_runtime.h>
#include <math.h>

#define S_TOTAL 13294
#define BATCHN 2
#define MTOT (BATCHN * S_TOTAL)   // 26588
#define DM 256
#define DF 1024

// ---------------- scratch (static device globals; no runtime allocation) -------------
__device__ float g_off[MTOT * DM];
__device__ float g_attn[MTOT * 128];
__device__ float g_val[MTOT * DM];
__device__ float g_ao[MTOT * DM];
__device__ float g_src2[MTOT * DM];
__device__ float g_x[MTOT * DM];
__device__ float g_h1[MTOT * DF];
__device__ float g_ff[MTOT * DM];

// packed fp32x2 FMA: d = a*b + d (per half, rn, bit-exact vs scalar fmaf)
__device__ __forceinline__ void ffma2(float2& d, const float2& a, const float2& b) {
    asm("fma.rn.f32x2 %0, %1, %2, %0;"
        : "+l"(reinterpret_cast<unsigned long long&>(d))
        : "l"(reinterpret_cast<const unsigned long long&>(a)),
          "l"(reinterpret_cast<const unsigned long long&>(b)));
}

// ---------------- SGEMM: C[M,N] = (A [+A2]) @ B[K,N] + bias, optional ReLU -----------
// 128x64 tile, BK=16, 256 threads, 8x4 microtile, f32x2 packed FMA.
template <int RELU, int ADD2>
__global__ void __launch_bounds__(256) sgemm(const float* __restrict__ A,
                                             const float* __restrict__ A2,
                                             const float* __restrict__ B,
                                             const float* __restrict__ bias,
                                             float* __restrict__ C,
                                             int M, int K, int N) {
    __shared__ float As[16][132];  // [k][m], 128 + 4 pad (row stride 528B, 16B-multiple)
    __shared__ float Bs[16][64];   // [k][n]

    const int t = threadIdx.x;
    const int tx = t & 15;         // col group: 4 cols
    const int ty = t >> 4;         // row group: 8 rows
    const int row0 = blockIdx.y * 128;
    const int col0 = blockIdx.x * 64;

    // A tile loaders: 128 rows x 16 cols = 512 float4; 2 per thread
    // idx = t*2 + i -> row = idx>>2, col = (idx&3)*4
    // B tile loaders: 16 rows x 64 cols = 256 float4; 1 per thread
    const int brow = t >> 4;
    const int bcol = (t & 15) << 2;

    float2 acc[4][4];  // acc[p][j]: rows (ty*8+2p, ty*8+2p+1), col tx*4+j
#pragma unroll
    for (int p = 0; p < 4; p++)
#pragma unroll
        for (int j = 0; j < 4; j++) acc[p][j] = make_float2(0.f, 0.f);

    for (int k0 = 0; k0 < K; k0 += 16) {
#pragma unroll
        for (int i = 0; i < 2; i++) {
            int idx = t * 2 + i;
            int ar = idx >> 2;
            int ac = (idx & 3) << 2;
            float4 av = make_float4(0.f, 0.f, 0.f, 0.f);
            if (row0 + ar < M) {
                av = *(const float4*)&A[(size_t)(row0 + ar) * K + k0 + ac];
                if (ADD2) {
                    float4 a2 = *(const float4*)&A2[(size_t)(row0 + ar) * K + k0 + ac];
                    av.x += a2.x; av.y += a2.y; av.z += a2.z; av.w += a2.w;
                }
            }
            As[ac + 0][ar] = av.x;
            As[ac + 1][ar] = av.y;
            As[ac + 2][ar] = av.z;
            As[ac + 3][ar] = av.w;
        }
        *(float4*)&Bs[brow][bcol] = *(const float4*)&B[(size_t)(k0 + brow) * N + col0 + bcol];

        __syncthreads();
#pragma unroll
        for (int k = 0; k < 16; k++) {
            float4 a_lo = *(const float4*)&As[k][ty * 8 + 0];
            float4 a_hi = *(const float4*)&As[k][ty * 8 + 4];
            float4 b4   = *(const float4*)&Bs[k][tx * 4];
            float2 ap[4];
            ap[0] = make_float2(a_lo.x, a_lo.y);
            ap[1] = make_float2(a_lo.z, a_lo.w);
            ap[2] = make_float2(a_hi.x, a_hi.y);
            ap[3] = make_float2(a_hi.z, a_hi.w);
            float2 br[4];
            br[0] = make_float2(b4.x, b4.x);
            br[1] = make_float2(b4.y, b4.y);
            br[2] = make_float2(b4.z, b4.z);
            br[3] = make_float2(b4.w, b4.w);
#pragma unroll
            for (int p = 0; p < 4; p++)
#pragma unroll
                for (int j = 0; j < 4; j++)
                    ffma2(acc[p][j], ap[p], br[j]);
        }
        __syncthreads();
    }

    float4 bb = *(const float4*)&bias[col0 + tx * 4];
#pragma unroll
    for (int p = 0; p < 4; p++) {
#pragma unroll
        for (int half = 0; half < 2; half++) {
            int row = row0 + ty * 8 + p * 2 + half;
            if (row < M) {
                float4 v;
                v.x = (half ? acc[p][0].y : acc[p][0].x) + bb.x;
                v.y = (half ? acc[p][1].y : acc[p][1].x) + bb.y;
                v.z = (half ? acc[p][2].y : acc[p][2].x) + bb.z;
                v.w = (half ? acc[p][3].y : acc[p][3].x) + bb.w;
                if (RELU) {
                    v.x = fmaxf(v.x, 0.f); v.y = fmaxf(v.y, 0.f);
                    v.z = fmaxf(v.z, 0.f); v.w = fmaxf(v.w, 0.f);
                }
                *(float4*)&C[(size_t)row * N + col0 + tx * 4] = v;
            }
        }
    }
}

// ---------------- MSDeformAttn sampling: softmax + bilinear + weighted sum -----------
// One block per (batch,token) row; warp h handles head h; lane = head-dim channel.
// Unconditional clamped gathers with mask-folded weights; 32-bit element offsets.
__global__ void __launch_bounds__(256) msda_sample(
    const float* __restrict__ refp,    // (N, S, 4, 2)
    const float* __restrict__ off,     // (rows, 256) = (h, l, p, 2)
    const float* __restrict__ attnlog, // (rows, 128) = (h, l*4+p)
    const float* __restrict__ value,   // (rows, 8, 32)
    float* __restrict__ out)           // (rows, 256)
{
    const int row = blockIdx.x;        // n*S + s
    const int h = threadIdx.x >> 5;
    const int n = (row >= S_TOTAL) ? 1 : 0;

    // softmax over 16 attention logits (warp-uniform)
    const float* al = attnlog + (size_t)row * 128 + h * 16;
    float l[16];
    float m = -1e30f;
#pragma unroll
    for (int j = 0; j < 16; j++) { l[j] = al[j]; m = fmaxf(m, l[j]); }
    float den = 0.f;
#pragma unroll
    for (int j = 0; j < 16; j++) { l[j] = __expf(l[j] - m); den += l[j]; }
    float inv = 1.f / den;

    const float* offp = off + (size_t)row * 256 + h * 32;
    const float* rp = refp + (size_t)row * 8;
    const float* vp = value + threadIdx.x;   // + h*32 + lane

    float acc = 0.f;
#pragma unroll
    for (int lv = 0; lv < 4; lv++) {
        const int H = (lv == 0) ? 100 : (lv == 1) ? 50 : (lv == 2) ? 25 : 13;
        const int W = H;
        const int start = (lv == 0) ? 0 : (lv == 1) ? 10000 : (lv == 2) ? 12500 : 13125;
        float rx = rp[lv * 2 + 0];
        float ry = rp[lv * 2 + 1];
        int base = n * S_TOTAL + start;
#pragma unroll
        for (int p = 0; p < 4; p++) {
            float ox = offp[(lv * 4 + p) * 2 + 0];
            float oy = offp[(lv * 4 + p) * 2 + 1];
            float x = (rx + ox / (float)W) * (float)W - 0.5f;
            float y = (ry + oy / (float)H) * (float)H - 0.5f;
            float x0f = floorf(x), y0f = floorf(y);
            int x0 = (int)x0f, y0 = (int)y0f;
            int x1 = x0 + 1, y1 = y0 + 1;
            float wx1 = x - x0f, wx0 = 1.f - wx1;
            float wy1 = y - y0f, wy0 = 1.f - wy1;
            float aw = l[lv * 4 + p] * inv;

            // validity masks folded into weights; addresses clamped -> unconditional loads
            float fx0 = ((unsigned)x0 < (unsigned)W) ? 1.f : 0.f;
            float fx1 = ((unsigned)x1 < (unsigned)W) ? 1.f : 0.f;
            float fy0 = ((unsigned)y0 < (unsigned)H) ? 1.f : 0.f;
            float fy1 = ((unsigned)y1 < (unsigned)H) ? 1.f : 0.f;
            int xc0 = min(max(x0, 0), W - 1);
            int xc1 = min(max(x1, 0), W - 1);
            int yc0 = min(max(y0, 0), H - 1);
            int yc1 = min(max(y1, 0), H - 1);

            int r00 = (base + yc0 * W + xc0) << 8;
            int r01 = (base + yc0 * W + xc1) << 8;
            int r10 = (base + yc1 * W + xc0) << 8;
            int r11 = (base + yc1 * W + xc1) << 8;

            float v00 = vp[r00];
            float v01 = vp[r01];
            float v10 = vp[r10];
            float v11 = vp[r11];

            float s = (wy0 * wx0 * fy0 * fx0) * v00
                    + (wy0 * wx1 * fy0 * fx1) * v01
                    + (wy1 * wx0 * fy1 * fx0) * v10
                    + (wy1 * wx1 * fy1 * fx1) * v11;
            acc += aw * s;
        }
    }
    out[(size_t)row * 256 + threadIdx.x] = acc;
}

// ---------------- fused residual add + LayerNorm (C = 256) ---------------------------
__global__ void __launch_bounds__(256) add_ln(const float* __restrict__ a,
                                              const float* __restrict__ b,
                                              const float* __restrict__ g,
                                              const float* __restrict__ be,
                                              float* __restrict__ out) {
    int row = blockIdx.x;
    int t = threadIdx.x;
    float v = a[(size_t)row * 256 + t] + b[(size_t)row * 256 + t];

    __shared__ float red[8];
    __shared__ float stat[2];

    float s = v;
#pragma unroll
    for (int o = 16; o; o >>= 1) s += __shfl_xor_sync(0xffffffffu, s, o);
    if ((t & 31) == 0) red[t >> 5] = s;
    __syncthreads();
    if (t == 0) {
        float tot = 0.f;
        for (int i = 0; i < 8; i++) tot += red[i];
        stat[0] = tot * (1.f / 256.f);
    }
    __syncthreads();
    float mean = stat[0];
    float d = v - mean;

    s = d * d;
#pragma unroll
    for (int o = 16; o; o >>= 1) s += __shfl_xor_sync(0xffffffffu, s, o);
    __syncthreads();
    if ((t & 31) == 0) red[t >> 5] = s;
    __syncthreads();
    if (t == 0) {
        float tot = 0.f;
        for (int i = 0; i < 8; i++) tot += red[i];
        stat[1] = tot * (1.f / 256.f);
    }
    __syncthreads();
    float var = stat[1];

    out[(size_t)row * 256 + t] = d * rsqrtf(var + 1e-5f) * g[t] + be[t];
}

// ---------------- launch -------------------------------------------------------------
extern "C" void kernel_launch(void* const* d_in, const int* in_sizes, int n_in,
                              void* d_out, int out_size) {
    const float* src   = (const float*)d_in[0];
    const float* pos   = (const float*)d_in[1];
    const float* refp  = (const float*)d_in[2];
    // d_in[3] spatial_shapes, d_in[4] level_start_index: static metadata, hardcoded
    const float* W_off  = (const float*)d_in[5];
    const float* b_off  = (const float*)d_in[6];
    const float* W_attn = (const float*)d_in[7];
    const float* b_attn = (const float*)d_in[8];
    const float* W_val  = (const float*)d_in[9];
    const float* b_val  = (const float*)d_in[10];
    const float* W_out  = (const float*)d_in[11];
    const float* b_out  = (const float*)d_in[12];
    const float* W1     = (const float*)d_in[13];
    const float* b1     = (const float*)d_in[14];
    const float* W2     = (const float*)d_in[15];
    const float* b2     = (const float*)d_in[16];
    const float* g1p    = (const float*)d_in[17];
    const float* be1p   = (const float*)d_in[18];
    const float* g2p    = (const float*)d_in[19];
    const float* be2p   = (const float*)d_in[20];
    float* out = (float*)d_out;

    float *offb, *attn, *val, *ao, *src2, *x, *h1, *ff;
    cudaGetSymbolAddress((void**)&offb, g_off);
    cudaGetSymbolAddress((void**)&attn, g_attn);
    cudaGetSymbolAddress((void**)&val, g_val);
    cudaGetSymbolAddress((void**)&ao, g_ao);
    cudaGetSymbolAddress((void**)&src2, g_src2);
    cudaGetSymbolAddress((void**)&x, g_x);
    cudaGetSymbolAddress((void**)&h1, g_h1);
    cudaGetSymbolAddress((void**)&ff, g_ff);

    const int M = MTOT;
    const int mby = (M + 127) / 128;

    // q = src + pos fused into the A-operand of the off/attn projections
    sgemm<0, 1><<<dim3(4, mby), 256>>>(src, pos, W_off, b_off, offb, M, 256, 256);
    sgemm<0, 1><<<dim3(2, mby), 256>>>(src, pos, W_attn, b_attn, attn, M, 256, 128);
    sgemm<0, 0><<<dim3(4, mby), 256>>>(src, nullptr, W_val, b_val, val, M, 256, 256);

    msda_sample<<<M, 256>>>(refp, offb, attn, val, ao);

    sgemm<0, 0><<<dim3(4, mby), 256>>>(ao, nullptr, W_out, b_out, src2, M, 256, 256);
    add_ln<<<M, 256>>>(src, src2, g1p, be1p, x);

    sgemm<1, 0><<<dim3(16, mby), 256>>>(x, nullptr, W1, b1, h1, M, 256, 1024);
    sgemm<0, 0><<<dim3(4, mby), 256>>>(h1, nullptr, W2, b2, ff, M, 1024, 256);
    add_ln<<<M, 256>>>(x, ff, g2p, be2p, out);
}